// round 10
// baseline (speedup 1.0000x reference)
#include <cuda_runtime.h>
#include <cuda_fp16.h>

// FixedFoveatedSensor: out[b,c,h,w] = sum_s bilinear(img, warp(pos_s)) * det_s / sum_s det_s
// img: (4,3,1024,1024) f32, t: (1,) f32, jitter: (16,256,256,2) f32, out: (4,3,256,256) f32
//
// Stage: planar fp32 -> y-pair-tiled interleaved fp16. Block of 64B per (x, y>>1):
//   [parity 0: ch0..11 + 4 pad halves][parity 1: ch0..11 + 4 pad halves]
// so a bilinear sample's y0/y1 corner records sit in the same (or adjacent) 128B line.
// Gather: warp = 1 sensor pixel; lanes = 16 spp x 2 channel-groups (A: ch0-7, B: ch8-11).
// Per thread: 4 corners x 1 LDG.128. Minimal warp footprint -> minimal L1 wavefronts.

#define SPP 16
#define SH 256
#define SW 256
#define NBC 12
#define IMG_H 1024
#define IMG_W 1024
#define BLOCK 256
#define PIX_PER_BLOCK 8          // 8 warps, 1 pixel per warp

__device__ __half g_img16[(size_t)IMG_H * IMG_W * 16];   // 32 MB, y-pair tiled

// ---------------- stage ----------------
__global__ __launch_bounds__(256)
void stage_kernel(const float* __restrict__ img)
{
    const int tid = blockIdx.x * 256 + threadIdx.x;      // 0 .. 524287
    const int x  = tid & (IMG_W - 1);
    const int yp = tid >> 10;                            // y-pair index

    uint4* dst = reinterpret_cast<uint4*>(g_img16) + (size_t)((yp << 10) | x) * 4;

#pragma unroll
    for (int parity = 0; parity < 2; parity++) {
        const int y = 2 * yp + parity;
        const size_t off = (size_t)y * IMG_W + x;
        unsigned u[8];
#pragma unroll
        for (int c = 0; c < 6; c++) {
            const float a = img[(size_t)(2 * c)     * (IMG_H * IMG_W) + off];
            const float b = img[(size_t)(2 * c + 1) * (IMG_H * IMG_W) + off];
            const __half2 h = __floats2half2_rn(a, b);
            u[c] = *reinterpret_cast<const unsigned*>(&h);
        }
        u[6] = 0u; u[7] = 0u;
        dst[parity * 2]     = make_uint4(u[0], u[1], u[2], u[3]);
        dst[parity * 2 + 1] = make_uint4(u[4], u[5], u[6], u[7]);
    }
}

// ---------------- gather ----------------
__device__ __forceinline__ size_t rec_idx(int x, int y, int grp)
{
    // uint4 index into g_img16 viewed as uint4[]
    return (size_t)(((y >> 1) << 10) | x) * 4 + ((y & 1) << 1) + grp;
}

__global__ __launch_bounds__(BLOCK)
void ffs_kernel(const float* __restrict__ t,
                const float* __restrict__ jitter,
                float* __restrict__ out)
{
    __shared__ float redA[PIX_PER_BLOCK][SPP][9];   // ch0-7 partial + det
    __shared__ float redB[PIX_PER_BLOCK][SPP][4];   // ch8-11 partial
    __shared__ float det_s[PIX_PER_BLOCK];

    const int tid  = threadIdx.x;
    const int wrp  = tid >> 5;               // pixel within block, 0..7
    const int lane = tid & 31;
    const int spp  = lane & 15;
    const int grp  = lane >> 4;              // 0: ch0-7, 1: ch8-11

    const int pixel = blockIdx.x * PIX_PER_BLOCK + wrp;
    const int h = pixel >> 8;
    const int w = pixel & 255;

    const float tt    = t[0];
    const float s_inv = 1.0f / tanhf(tt);
    const float step  = 2.0f / 256.0f;

    const float2 jit = ((const float2*)jitter)[((size_t)spp * SH + h) * SW + w];
    const float posx = fmaf(jit.x, step, -1.0f + (float)w * step);
    const float posy = fmaf(jit.y, step, -1.0f + (float)h * step);

    const float thx = tanhf(tt * posx);
    const float thy = tanhf(tt * posy);
    const float wrx = thx * s_inv;
    const float wry = thy * s_inv;
    const float ddx = tt * (1.0f - thx * thx) * s_inv;
    const float ddy = tt * (1.0f - thy * thy) * s_inv;
    const float det = ddx * ddy;

    float gx = (wrx + 1.0f) * (0.5f * IMG_W) - 0.5f;
    float gy = (wry + 1.0f) * (0.5f * IMG_H) - 0.5f;
    gx = fminf(fmaxf(gx, 0.0f), (float)(IMG_W - 1));
    gy = fminf(fmaxf(gy, 0.0f), (float)(IMG_H - 1));
    const float x0f = floorf(gx);
    const float y0f = floorf(gy);
    const float fx = gx - x0f;
    const float fy = gy - y0f;
    const int x0 = (int)x0f;
    const int y0 = (int)y0f;
    const int x1 = min(x0 + 1, IMG_W - 1);
    const int y1 = min(y0 + 1, IMG_H - 1);

    const float w11 = fx * fy * det;
    const float w01 = fx * det - w11;
    const float w10 = fy * det - w11;
    const float w00 = det - w01 - w10 - w11;

    const uint4* __restrict__ base4 = reinterpret_cast<const uint4*>(g_img16);

    float acc[8];
#pragma unroll
    for (int j = 0; j < 8; j++) acc[j] = 0.0f;

    {
        const size_t rr[4] = { rec_idx(x0, y0, grp), rec_idx(x1, y0, grp),
                               rec_idx(x0, y1, grp), rec_idx(x1, y1, grp) };
        const float  ww[4] = { w00, w01, w10, w11 };
#pragma unroll
        for (int c = 0; c < 4; c++) {
            const uint4 v = base4[rr[c]];
            const unsigned uu[4] = { v.x, v.y, v.z, v.w };
            const float wc = ww[c];
#pragma unroll
            for (int q = 0; q < 4; q++) {
                const float2 f = __half22float2(*reinterpret_cast<const __half2*>(&uu[q]));
                acc[2 * q]     = fmaf(f.x, wc, acc[2 * q]);
                acc[2 * q + 1] = fmaf(f.y, wc, acc[2 * q + 1]);
            }
        }
    }

    if (grp == 0) {
#pragma unroll
        for (int j = 0; j < 8; j++) redA[wrp][spp][j] = acc[j];
        redA[wrp][spp][8] = det;
    } else {
#pragma unroll
        for (int j = 0; j < 4; j++) redB[wrp][spp][j] = acc[j];
    }
    __syncthreads();

    // 8 pixels x 13 values = 104 sum-threads
    float sum = 0.0f;
    int p = 0, j = 0;
    if (tid < PIX_PER_BLOCK * 13) {
        p = tid / 13;
        j = tid - p * 13;
        if (j < 8) {
#pragma unroll
            for (int k = 0; k < SPP; k++) sum += redA[p][k][j];
        } else if (j < 12) {
#pragma unroll
            for (int k = 0; k < SPP; k++) sum += redB[p][k][j - 8];
        } else {
#pragma unroll
            for (int k = 0; k < SPP; k++) sum += redA[p][k][8];
            det_s[p] = sum;
        }
    }
    __syncthreads();

    if (tid < PIX_PER_BLOCK * 13 && j < NBC) {
        const int opix = blockIdx.x * PIX_PER_BLOCK + p;
        out[(size_t)j * (SH * SW) + opix] = sum / det_s[p];
    }
}

extern "C" void kernel_launch(void* const* d_in, const int* in_sizes, int n_in,
                              void* d_out, int out_size)
{
    const float* img    = (const float*)d_in[0];
    const float* t      = (const float*)d_in[1];
    const float* jitter = (const float*)d_in[2];
    float* out          = (float*)d_out;

    stage_kernel<<<(IMG_H * IMG_W / 2) / 256, 256>>>(img);
    ffs_kernel<<<(SH * SW) / PIX_PER_BLOCK, BLOCK>>>(t, jitter, out);
}

// round 11
// speedup vs baseline: 1.3816x; 1.3816x over previous
#include <cuda_runtime.h>
#include <cuda_fp16.h>

// FixedFoveatedSensor: out[b,c,h,w] = sum_s bilinear(img, warp(pos_s)) * det_s / sum_s det_s
// img: (4,3,1024,1024) f32, t: (1,) f32, jitter: (16,256,256,2) f32, out: (4,3,256,256) f32
//
// Stage: planar fp32 -> two flat interleaved fp16 buffers (no padding):
//   b0[y*1024+x] = uint4  (ch0..7,  16 B)  -> 8 records / 128B line
//   b1[y*1024+x] = uint2  (ch8..11,  8 B)  -> 16 records / 128B line
// Gather (R9 structure): warp = 2 px x 16 spp, 1 thread = 1 full sample;
// per corner: 1 LDG.128 (b0) + 1 LDG.64 (b1). 96 B/sample gathered.

#define SPP 16
#define SH 256
#define SW 256
#define NBC 12
#define NVALS 13
#define PIX_PER_BLOCK 8
#define BLOCK 128
#define IMG_H 1024
#define IMG_W 1024
#define NPIX (IMG_H * IMG_W)

__device__ uint4 g_b0[NPIX];   // 16 MB: ch0-7 fp16
__device__ uint2 g_b1[NPIX];   // 8 MB:  ch8-11 fp16

// ---------------- stage: 4 pixels per thread ----------------
__global__ __launch_bounds__(256)
void stage_kernel(const float* __restrict__ img)
{
    const int px0 = (blockIdx.x * 256 + threadIdx.x) * 4;   // 4 consecutive pixels

    float4 v[NBC];
#pragma unroll
    for (int c = 0; c < NBC; c++)
        v[c] = *reinterpret_cast<const float4*>(img + (size_t)c * NPIX + px0);

    const float* f = reinterpret_cast<const float*>(v);     // f[c*4 + k]

#pragma unroll
    for (int k = 0; k < 4; k++) {
        unsigned u0[4], u1[2];
#pragma unroll
        for (int q = 0; q < 4; q++) {
            const __half2 h = __floats2half2_rn(f[(2 * q) * 4 + k], f[(2 * q + 1) * 4 + k]);
            u0[q] = *reinterpret_cast<const unsigned*>(&h);
        }
#pragma unroll
        for (int q = 0; q < 2; q++) {
            const __half2 h = __floats2half2_rn(f[(8 + 2 * q) * 4 + k], f[(9 + 2 * q) * 4 + k]);
            u1[q] = *reinterpret_cast<const unsigned*>(&h);
        }
        g_b0[px0 + k] = make_uint4(u0[0], u0[1], u0[2], u0[3]);
        g_b1[px0 + k] = make_uint2(u1[0], u1[1]);
    }
}

// ---------------- gather ----------------
__global__ __launch_bounds__(BLOCK)
void ffs_kernel(const float* __restrict__ t,
                const float* __restrict__ jitter,
                float* __restrict__ out)
{
    __shared__ float red[BLOCK * NVALS];
    __shared__ float det_s[PIX_PER_BLOCK];

    const int tid  = threadIdx.x;
    const int spp  = tid & 15;
    const int pin  = tid >> 4;
    const int pixel = blockIdx.x * PIX_PER_BLOCK + pin;
    const int h = pixel >> 8;
    const int w = pixel & 255;

    const float tt    = t[0];
    const float s_inv = 1.0f / tanhf(tt);
    const float step  = 2.0f / 256.0f;

    const float2 jit = ((const float2*)jitter)[((size_t)spp * SH + h) * SW + w];
    const float posx = fmaf(jit.x, step, -1.0f + (float)w * step);
    const float posy = fmaf(jit.y, step, -1.0f + (float)h * step);

    const float thx = tanhf(tt * posx);
    const float thy = tanhf(tt * posy);
    const float wrx = thx * s_inv;
    const float wry = thy * s_inv;
    const float ddx = tt * (1.0f - thx * thx) * s_inv;
    const float ddy = tt * (1.0f - thy * thy) * s_inv;
    const float det = ddx * ddy;

    float gx = (wrx + 1.0f) * (0.5f * IMG_W) - 0.5f;
    float gy = (wry + 1.0f) * (0.5f * IMG_H) - 0.5f;
    gx = fminf(fmaxf(gx, 0.0f), (float)(IMG_W - 1));
    gy = fminf(fmaxf(gy, 0.0f), (float)(IMG_H - 1));
    const float x0f = floorf(gx);
    const float y0f = floorf(gy);
    const float fx = gx - x0f;
    const float fy = gy - y0f;
    const int x0 = (int)x0f;
    const int y0 = (int)y0f;
    const int x1 = min(x0 + 1, IMG_W - 1);
    const int y1 = min(y0 + 1, IMG_H - 1);

    const float w11 = fx * fy * det;
    const float w01 = fx * det - w11;
    const float w10 = fy * det - w11;
    const float w00 = det - w01 - w10 - w11;

    const int i00 = y0 * IMG_W + x0;
    const int i01 = y0 * IMG_W + x1;
    const int i10 = y1 * IMG_W + x0;
    const int i11 = y1 * IMG_W + x1;

    float acc[NBC];
#pragma unroll
    for (int j = 0; j < NBC; j++) acc[j] = 0.0f;

    {
        const int   ii[4] = { i00, i01, i10, i11 };
        const float ww[4] = { w00, w01, w10, w11 };
#pragma unroll
        for (int c = 0; c < 4; c++) {
            const uint4 a = g_b0[ii[c]];
            const uint2 b = g_b1[ii[c]];
            const unsigned uu[6] = { a.x, a.y, a.z, a.w, b.x, b.y };
            const float wc = ww[c];
#pragma unroll
            for (int q = 0; q < 6; q++) {
                const float2 f = __half22float2(*reinterpret_cast<const __half2*>(&uu[q]));
                acc[2 * q]     = fmaf(f.x, wc, acc[2 * q]);
                acc[2 * q + 1] = fmaf(f.y, wc, acc[2 * q + 1]);
            }
        }
    }

#pragma unroll
    for (int j = 0; j < NBC; j++) red[tid * NVALS + j] = acc[j];
    red[tid * NVALS + NBC] = det;
    __syncthreads();

    float sum = 0.0f;
    int p = 0, j = 0;
    if (tid < PIX_PER_BLOCK * NVALS) {
        p = tid / NVALS;
        j = tid - p * NVALS;
        const float* b2 = red + (p * SPP) * NVALS + j;
#pragma unroll
        for (int k = 0; k < SPP; k++) sum += b2[k * NVALS];
        if (j == NBC) det_s[p] = sum;
    }
    __syncthreads();

    if (tid < PIX_PER_BLOCK * NVALS && j < NBC) {
        const int opix = blockIdx.x * PIX_PER_BLOCK + p;
        out[(size_t)j * (SH * SW) + opix] = sum / det_s[p];
    }
}

extern "C" void kernel_launch(void* const* d_in, const int* in_sizes, int n_in,
                              void* d_out, int out_size)
{
    const float* img    = (const float*)d_in[0];
    const float* t      = (const float*)d_in[1];
    const float* jitter = (const float*)d_in[2];
    float* out          = (float*)d_out;

    stage_kernel<<<NPIX / (256 * 4), 256>>>(img);
    ffs_kernel<<<(SH * SW) / PIX_PER_BLOCK, BLOCK>>>(t, jitter, out);
}

// round 12
// speedup vs baseline: 1.4705x; 1.0644x over previous
#include <cuda_runtime.h>
#include <cuda_fp16.h>

// FixedFoveatedSensor: out[b,c,h,w] = sum_s bilinear(img, warp(pos_s)) * det_s / sum_s det_s
// img: (4,3,1024,1024) f32, t: (1,) f32, jitter: (16,256,256,2) f32, out: (4,3,256,256) f32
//
// Stage: planar fp32 -> two flat interleaved fp16 buffers (no padding):
//   b0[y*1024+x] = uint4 (ch0..7, 16 B), b1[y*1024+x] = uint2 (ch8..11, 8 B)
// Gather: warp = 2 px x 16 spp, 1 thread = 1 full sample; per corner 1 LDG.128 + 1 LDG.64.
// NEW: jitter staged through smem with a coalesced block load (block = 16 px), removing
// the 16-wavefront strided jitter LDG from every warp (was ~15% of L1 wavefront budget).

#define SPP 16
#define SH 256
#define SW 256
#define NBC 12
#define NVALS 13
#define PIX_PER_BLOCK 16
#define BLOCK 256
#define IMG_H 1024
#define IMG_W 1024
#define NPIX (IMG_H * IMG_W)

__device__ uint4 g_b0[NPIX];   // 16 MB: ch0-7 fp16
__device__ uint2 g_b1[NPIX];   // 8 MB:  ch8-11 fp16

// ---------------- stage: 4 pixels per thread ----------------
__global__ __launch_bounds__(256)
void stage_kernel(const float* __restrict__ img)
{
    const int px0 = (blockIdx.x * 256 + threadIdx.x) * 4;

    float4 v[NBC];
#pragma unroll
    for (int c = 0; c < NBC; c++)
        v[c] = *reinterpret_cast<const float4*>(img + (size_t)c * NPIX + px0);

    const float* f = reinterpret_cast<const float*>(v);     // f[c*4 + k]

#pragma unroll
    for (int k = 0; k < 4; k++) {
        unsigned u0[4], u1[2];
#pragma unroll
        for (int q = 0; q < 4; q++) {
            const __half2 h = __floats2half2_rn(f[(2 * q) * 4 + k], f[(2 * q + 1) * 4 + k]);
            u0[q] = *reinterpret_cast<const unsigned*>(&h);
        }
#pragma unroll
        for (int q = 0; q < 2; q++) {
            const __half2 h = __floats2half2_rn(f[(8 + 2 * q) * 4 + k], f[(9 + 2 * q) * 4 + k]);
            u1[q] = *reinterpret_cast<const unsigned*>(&h);
        }
        g_b0[px0 + k] = make_uint4(u0[0], u0[1], u0[2], u0[3]);
        g_b1[px0 + k] = make_uint2(u1[0], u1[1]);
    }
}

// ---------------- gather ----------------
__global__ __launch_bounds__(BLOCK)
void ffs_kernel(const float* __restrict__ t,
                const float* __restrict__ jitter,
                float* __restrict__ out)
{
    __shared__ float2 jit_s[SPP][PIX_PER_BLOCK + 1];  // +1 pad: cut bank conflicts
    __shared__ float  red[BLOCK * NVALS];             // 13.3 KB
    __shared__ float  det_s[PIX_PER_BLOCK];

    const int tid = threadIdx.x;
    const int pixelBase = blockIdx.x * PIX_PER_BLOCK;

    // coalesced jitter load: 16 spp-rows x 16 px x 8 B = one 128B line per row
    {
        const int s = tid >> 4;
        const int p = tid & 15;
        jit_s[s][p] = ((const float2*)jitter)[(size_t)s * (SH * SW) + pixelBase + p];
    }
    __syncthreads();

    const int spp = tid & 15;
    const int pin = tid >> 4;
    const int pixel = pixelBase + pin;
    const int h = pixel >> 8;
    const int w = pixel & 255;

    const float tt    = t[0];
    const float s_inv = 1.0f / tanhf(tt);
    const float step  = 2.0f / 256.0f;

    const float2 jit = jit_s[spp][pin];
    const float posx = fmaf(jit.x, step, -1.0f + (float)w * step);
    const float posy = fmaf(jit.y, step, -1.0f + (float)h * step);

    const float thx = tanhf(tt * posx);
    const float thy = tanhf(tt * posy);
    const float wrx = thx * s_inv;
    const float wry = thy * s_inv;
    const float ddx = tt * (1.0f - thx * thx) * s_inv;
    const float ddy = tt * (1.0f - thy * thy) * s_inv;
    const float det = ddx * ddy;

    float gx = (wrx + 1.0f) * (0.5f * IMG_W) - 0.5f;
    float gy = (wry + 1.0f) * (0.5f * IMG_H) - 0.5f;
    gx = fminf(fmaxf(gx, 0.0f), (float)(IMG_W - 1));
    gy = fminf(fmaxf(gy, 0.0f), (float)(IMG_H - 1));
    const float x0f = floorf(gx);
    const float y0f = floorf(gy);
    const float fx = gx - x0f;
    const float fy = gy - y0f;
    const int x0 = (int)x0f;
    const int y0 = (int)y0f;
    const int x1 = min(x0 + 1, IMG_W - 1);
    const int y1 = min(y0 + 1, IMG_H - 1);

    const float w11 = fx * fy * det;
    const float w01 = fx * det - w11;
    const float w10 = fy * det - w11;
    const float w00 = det - w01 - w10 - w11;

    const int i00 = y0 * IMG_W + x0;
    const int i01 = y0 * IMG_W + x1;
    const int i10 = y1 * IMG_W + x0;
    const int i11 = y1 * IMG_W + x1;

    float acc[NBC];
#pragma unroll
    for (int j = 0; j < NBC; j++) acc[j] = 0.0f;

    {
        const int   ii[4] = { i00, i01, i10, i11 };
        const float ww[4] = { w00, w01, w10, w11 };
#pragma unroll
        for (int c = 0; c < 4; c++) {
            const uint4 a = g_b0[ii[c]];
            const uint2 b = g_b1[ii[c]];
            const unsigned uu[6] = { a.x, a.y, a.z, a.w, b.x, b.y };
            const float wc = ww[c];
#pragma unroll
            for (int q = 0; q < 6; q++) {
                const float2 f = __half22float2(*reinterpret_cast<const __half2*>(&uu[q]));
                acc[2 * q]     = fmaf(f.x, wc, acc[2 * q]);
                acc[2 * q + 1] = fmaf(f.y, wc, acc[2 * q + 1]);
            }
        }
    }

#pragma unroll
    for (int j = 0; j < NBC; j++) red[tid * NVALS + j] = acc[j];
    red[tid * NVALS + NBC] = det;
    __syncthreads();

    // 16 px x 13 values = 208 sum-threads, each sums its value over 16 spp
    float sum = 0.0f;
    int p = 0, j = 0;
    if (tid < PIX_PER_BLOCK * NVALS) {
        p = tid / NVALS;
        j = tid - p * NVALS;
        const float* b2 = red + (p * SPP) * NVALS + j;
#pragma unroll
        for (int k = 0; k < SPP; k++) sum += b2[k * NVALS];
        if (j == NBC) det_s[p] = sum;
    }
    __syncthreads();

    if (tid < PIX_PER_BLOCK * NVALS && j < NBC) {
        const int opix = pixelBase + p;
        out[(size_t)j * (SH * SW) + opix] = sum / det_s[p];
    }
}

extern "C" void kernel_launch(void* const* d_in, const int* in_sizes, int n_in,
                              void* d_out, int out_size)
{
    const float* img    = (const float*)d_in[0];
    const float* t      = (const float*)d_in[1];
    const float* jitter = (const float*)d_in[2];
    float* out          = (float*)d_out;

    stage_kernel<<<NPIX / (256 * 4), 256>>>(img);
    ffs_kernel<<<(SH * SW) / PIX_PER_BLOCK, BLOCK>>>(t, jitter, out);
}